// round 1
// baseline (speedup 1.0000x reference)
#include <cuda_runtime.h>

#define NB    4
#define SEQ   2048
#define DIM   1024
#define HEADS 8
#define HD    128
#define MROWS (NB*SEQ)

// Scratch (device globals — no allocation allowed)
__device__ float g_v  [(size_t)NB*HEADS*SEQ*HD];
__device__ float g_ek [(size_t)NB*HEADS*SEQ*HD];
__device__ float g_ekv[(size_t)NB*HEADS*SEQ*HD];
__device__ float g_aft[(size_t)MROWS*DIM];

#define MODE_V   0
#define MODE_K   1
#define MODE_OUT 2

// C[M=8192, N=1024] = A[8192,1024] @ B[1024,1024] + bias, fp32 SIMT.
// Tile 64x64, BK=16, 256 threads, 4x4 per thread.
template<int MODE>
__global__ __launch_bounds__(256)
void gemm_kernel(const float* __restrict__ Ain, const float* __restrict__ B,
                 const float* __restrict__ bias, float* __restrict__ out)
{
    __shared__ float As[16][64];   // [k][m]
    __shared__ float Bs[16][64];   // [k][n]
    const float* A = (MODE == MODE_OUT) ? (const float*)g_aft : Ain;

    const int tid = threadIdx.x;
    const int bx = blockIdx.x;     // col tile (16)
    const int by = blockIdx.y;     // row tile (128)
    const int tx = tid & 15;       // 0..15
    const int ty = tid >> 4;       // 0..15

    const int arow = tid >> 2;            // 0..63
    const int acol = (tid & 3) << 2;      // 0,4,8,12
    const int brow = tid >> 4;            // 0..15
    const int bcol = (tid & 15) << 2;     // 0..60

    const float* Aptr = A + (size_t)(by*64 + arow)*DIM + acol;
    const float* Bptr = B + (size_t)brow*DIM + bx*64 + bcol;

    float acc[4][4] = {};

    for (int k0 = 0; k0 < DIM; k0 += 16) {
        float4 a4 = *(const float4*)(Aptr + k0);
        As[acol+0][arow] = a4.x;
        As[acol+1][arow] = a4.y;
        As[acol+2][arow] = a4.z;
        As[acol+3][arow] = a4.w;
        *(float4*)&Bs[brow][bcol] = *(const float4*)(Bptr + (size_t)k0*DIM);
        __syncthreads();

        #pragma unroll
        for (int k = 0; k < 16; k++) {
            float4 av = *(const float4*)&As[k][ty << 2];
            float4 bv = *(const float4*)&Bs[k][tx << 2];
            float ar[4] = {av.x, av.y, av.z, av.w};
            float br[4] = {bv.x, bv.y, bv.z, bv.w};
            #pragma unroll
            for (int i = 0; i < 4; i++)
                #pragma unroll
                for (int j = 0; j < 4; j++)
                    acc[i][j] += ar[i]*br[j];
        }
        __syncthreads();
    }

    #pragma unroll
    for (int i = 0; i < 4; i++) {
        const int r = by*64 + (ty << 2) + i;     // 0..8191
        const int n = r >> 11;                   // /SEQ
        const int s = r & (SEQ-1);
        #pragma unroll
        for (int j = 0; j < 4; j++) {
            const int o = bx*64 + (tx << 2) + j; // 0..1023
            const float val = acc[i][j] + bias[o];
            if (MODE == MODE_OUT) {
                out[(size_t)r*DIM + o] = val;
            } else {
                const int h = o >> 7, d = o & 127;
                const size_t idx = (((size_t)(n*HEADS + h))*SEQ + s)*HD + d;
                if (MODE == MODE_V) {
                    g_v[idx] = val;
                } else {
                    const float e = __expf(val);
                    g_ek[idx]  = e;
                    g_ekv[idx] = e * g_v[idx];
                }
            }
        }
    }
}

// AFT core: for each (n,h), tile of 32 t-rows x 128 d-cols.
//   num[t,d] = sum_{s<=t} exp(w[h,t,s]) * ekv[n,h,s,d]
//   den[t,d] = sum_{s<=t} exp(w[h,t,s]) * ek [n,h,s,d]
//   aft = num/den written to g_aft[(n*SEQ+t)*DIM + h*HD + d]
__global__ __launch_bounds__(256)
void aft_kernel(const float* __restrict__ w_aft)
{
    __shared__ float wsT [32][32];   // [s][t] = exp(w) masked
    __shared__ float eks [32][128];  // [s][d]
    __shared__ float ekvs[32][128];

    const int tid = threadIdx.x;
    const int nh = blockIdx.y;            // 0..31  (= n*HEADS + h)
    const int n  = nh >> 3;
    const int h  = nh & 7;
    const int t0 = blockIdx.x << 5;       // t tile base

    const int tx = tid & 31;              // d groups: d = tx*4..+3
    const int ty = tid >> 5;              // t groups: t = ty*4..+3 (0..7)

    const float* wbase   = w_aft + ((size_t)h*SEQ + t0)*SEQ;
    const float* ekbase  = g_ek  + (size_t)nh*SEQ*HD;
    const float* ekvbase = g_ekv + (size_t)nh*SEQ*HD;

    // load mappings
    const int w_tl = tid >> 3;            // 0..31 (t-local)
    const int w_sl = (tid & 7) << 2;      // 0..28 (s-local, x4)
    const int e_sl = tid >> 3;            // 0..31 (s-local)
    const int e_c  = (tid & 7) << 2;      // 0..28 (d base, x4)

    float accN[4][4] = {};
    float accD[4][4] = {};

    const int nchunks = (t0 >> 5) + 1;    // s chunks up to & incl. diagonal
    for (int c = 0; c < nchunks; c++) {
        const int s0 = c << 5;

        // exp(w) tile, causal-masked, stored transposed [s][t]
        float4 w4 = *(const float4*)(wbase + (size_t)w_tl*SEQ + s0 + w_sl);
        const int tg = t0 + w_tl;
        wsT[w_sl+0][w_tl] = (s0 + w_sl + 0 <= tg) ? __expf(w4.x) : 0.f;
        wsT[w_sl+1][w_tl] = (s0 + w_sl + 1 <= tg) ? __expf(w4.y) : 0.f;
        wsT[w_sl+2][w_tl] = (s0 + w_sl + 2 <= tg) ? __expf(w4.z) : 0.f;
        wsT[w_sl+3][w_tl] = (s0 + w_sl + 3 <= tg) ? __expf(w4.w) : 0.f;

        const float* ekp  = ekbase  + (size_t)(s0 + e_sl)*HD + e_c;
        const float* ekvp = ekvbase + (size_t)(s0 + e_sl)*HD + e_c;
        #pragma unroll
        for (int j = 0; j < 4; j++) {
            *(float4*)&eks [e_sl][e_c + 32*j] = *(const float4*)(ekp  + 32*j);
            *(float4*)&ekvs[e_sl][e_c + 32*j] = *(const float4*)(ekvp + 32*j);
        }
        __syncthreads();

        #pragma unroll
        for (int s = 0; s < 32; s++) {
            float4 a4  = *(const float4*)&wsT [s][ty << 2];
            float4 bk4 = *(const float4*)&eks [s][tx << 2];
            float4 bv4 = *(const float4*)&ekvs[s][tx << 2];
            float ar[4]  = {a4.x,  a4.y,  a4.z,  a4.w};
            float bkr[4] = {bk4.x, bk4.y, bk4.z, bk4.w};
            float bvr[4] = {bv4.x, bv4.y, bv4.z, bv4.w};
            #pragma unroll
            for (int i = 0; i < 4; i++)
                #pragma unroll
                for (int j = 0; j < 4; j++) {
                    accN[i][j] += ar[i]*bvr[j];
                    accD[i][j] += ar[i]*bkr[j];
                }
        }
        __syncthreads();
    }

    #pragma unroll
    for (int i = 0; i < 4; i++) {
        const int t = t0 + (ty << 2) + i;
        #pragma unroll
        for (int j = 0; j < 4; j++) {
            const int d = (tx << 2) + j;
            g_aft[((size_t)(n*SEQ + t))*DIM + h*HD + d] = accN[i][j] / accD[i][j];
        }
    }
}

extern "C" void kernel_launch(void* const* d_in, const int* in_sizes, int n_in,
                              void* d_out, int out_size)
{
    const float* x     = (const float*)d_in[0];
    const float* Wk    = (const float*)d_in[1];
    const float* bk    = (const float*)d_in[2];
    const float* Wv    = (const float*)d_in[3];
    const float* bv    = (const float*)d_in[4];
    const float* w_aft = (const float*)d_in[5];
    const float* Wo    = (const float*)d_in[6];
    const float* bo    = (const float*)d_in[7];
    float* out = (float*)d_out;

    dim3 gg(DIM/64, MROWS/64);                 // (16, 128)
    gemm_kernel<MODE_V><<<gg, 256>>>(x, Wv, bv, nullptr);
    gemm_kernel<MODE_K><<<gg, 256>>>(x, Wk, bk, nullptr);
    aft_kernel<<<dim3(SEQ/32, NB*HEADS), 256>>>(w_aft);
    gemm_kernel<MODE_OUT><<<gg, 256>>>(nullptr, Wo, bo, out);
}

// round 2
// speedup vs baseline: 2.0918x; 2.0918x over previous
#include <cuda_runtime.h>
#include <cstdint>

#define NB    4
#define SEQ   2048
#define DIM   1024
#define HEADS 8
#define HD    128
#define MROWS (NB*SEQ)

// Scratch (device globals — no allocation allowed)
__device__ float g_v  [(size_t)NB*HEADS*SEQ*HD];
__device__ float g_ek [(size_t)NB*HEADS*SEQ*HD];
__device__ float g_ekv[(size_t)NB*HEADS*SEQ*HD];
__device__ float g_aft[(size_t)MROWS*DIM];

#define MODE_V   0
#define MODE_K   1
#define MODE_OUT 2

__device__ __forceinline__ uint32_t f2tf32(float x) {
    uint32_t r;
    asm("cvt.rna.tf32.f32 %0, %1;" : "=r"(r) : "f"(x));
    return r;
}

__device__ __forceinline__ void mma_tf32(float c[4],
    uint32_t a0, uint32_t a1, uint32_t a2, uint32_t a3,
    uint32_t b0, uint32_t b1)
{
    asm volatile(
        "mma.sync.aligned.m16n8k8.row.col.f32.tf32.tf32.f32 "
        "{%0,%1,%2,%3}, {%4,%5,%6,%7}, {%8,%9}, {%0,%1,%2,%3};\n"
        : "+f"(c[0]), "+f"(c[1]), "+f"(c[2]), "+f"(c[3])
        : "r"(a0), "r"(a1), "r"(a2), "r"(a3), "r"(b0), "r"(b1));
}

#define SPAD 136   // smem row stride in words; (8c+r) mod 32 is conflict-free

// ---------------------------------------------------------------------------
// C[8192,1024] = A[8192,1024] @ B[1024,1024] + bias, tf32 tensor cores.
// Block 128x128, BK=16, 256 threads, warps 2(m) x 4(n), warp tile 64x32.
// ---------------------------------------------------------------------------
template<int MODE>
__global__ __launch_bounds__(256)
void gemm_tc(const float* __restrict__ Ain, const float* __restrict__ B,
             const float* __restrict__ bias, float* __restrict__ out)
{
    __shared__ uint32_t As[2][16][SPAD];   // [k][m], tf32 bits
    __shared__ uint32_t Bs[2][16][SPAD];   // [k][n], tf32 bits

    const float* A = (MODE == MODE_OUT) ? (const float*)g_aft : Ain;

    const int tid  = threadIdx.x;
    const int lane = tid & 31;
    const int warp = tid >> 5;
    const int wm   = warp >> 2;        // 0..1
    const int wn   = warp & 3;         // 0..3
    const int r    = lane >> 2;        // 0..7
    const int cc   = lane & 3;         // 0..3

    const int bm = blockIdx.y << 7;
    const int bn = blockIdx.x << 7;

    // global load mapping: 512 float4 per tile, 2 per thread
    // A: float4 index g: m = g>>2, k4 = (g&3)*4
    // B: float4 index g: k = g>>5, n4 = (g&31)*4
    float4 aReg[2], bReg[2];

    const float* Abase = A + (size_t)bm * DIM;
    const float* Bbase = B + bn;

    auto loadTile = [&](int k0) {
        #pragma unroll
        for (int i = 0; i < 2; i++) {
            int g = tid + (i << 8);
            aReg[i] = *(const float4*)(Abase + (size_t)(g >> 2) * DIM + k0 + ((g & 3) << 2));
            bReg[i] = *(const float4*)(Bbase + (size_t)(k0 + (g >> 5)) * DIM + ((g & 31) << 2));
        }
    };
    auto storeTile = [&](int buf) {
        #pragma unroll
        for (int i = 0; i < 2; i++) {
            int g = tid + (i << 8);
            int m = g >> 2, k4 = (g & 3) << 2;
            As[buf][k4 + 0][m] = f2tf32(aReg[i].x);
            As[buf][k4 + 1][m] = f2tf32(aReg[i].y);
            As[buf][k4 + 2][m] = f2tf32(aReg[i].z);
            As[buf][k4 + 3][m] = f2tf32(aReg[i].w);
            int k = g >> 5, n4 = (g & 31) << 2;
            uint4 b4;
            b4.x = f2tf32(bReg[i].x); b4.y = f2tf32(bReg[i].y);
            b4.z = f2tf32(bReg[i].z); b4.w = f2tf32(bReg[i].w);
            *(uint4*)&Bs[buf][k][n4] = b4;
        }
    };

    float acc[4][4][4] = {};   // [im][in][4]

    loadTile(0);
    storeTile(0);
    __syncthreads();

    const int NT = DIM / 16;   // 64
    for (int kt = 0; kt < NT; kt++) {
        const int buf = kt & 1;
        if (kt + 1 < NT) loadTile((kt + 1) << 4);

        #pragma unroll
        for (int ks = 0; ks < 2; ks++) {
            const int k8 = ks << 3;
            uint32_t af[4][4], bf[4][2];
            #pragma unroll
            for (int im = 0; im < 4; im++) {
                const int m0 = (wm << 6) + (im << 4);
                af[im][0] = As[buf][k8 + cc    ][m0 + r    ];
                af[im][1] = As[buf][k8 + cc    ][m0 + r + 8];
                af[im][2] = As[buf][k8 + cc + 4][m0 + r    ];
                af[im][3] = As[buf][k8 + cc + 4][m0 + r + 8];
            }
            #pragma unroll
            for (int in = 0; in < 4; in++) {
                const int n0 = (wn << 5) + (in << 3);
                bf[in][0] = Bs[buf][k8 + cc    ][n0 + r];
                bf[in][1] = Bs[buf][k8 + cc + 4][n0 + r];
            }
            #pragma unroll
            for (int im = 0; im < 4; im++)
                #pragma unroll
                for (int in = 0; in < 4; in++)
                    mma_tf32(acc[im][in], af[im][0], af[im][1], af[im][2], af[im][3],
                             bf[in][0], bf[in][1]);
        }

        if (kt + 1 < NT) { storeTile(buf ^ 1); }
        __syncthreads();
    }

    // epilogue
    #pragma unroll
    for (int im = 0; im < 4; im++) {
        #pragma unroll
        for (int in = 0; in < 4; in++) {
            #pragma unroll
            for (int e = 0; e < 4; e++) {
                const int row = bm + (wm << 6) + (im << 4) + r + ((e >> 1) << 3);
                const int col = bn + (wn << 5) + (in << 3) + (cc << 1) + (e & 1);
                const float val = acc[im][in][e] + bias[col];
                if (MODE == MODE_OUT) {
                    out[(size_t)row * DIM + col] = val;
                } else {
                    const int n = row >> 11, s = row & (SEQ - 1);
                    const int h = col >> 7, d = col & 127;
                    const size_t idx = (((size_t)(n * HEADS + h)) * SEQ + s) * HD + d;
                    if (MODE == MODE_V) {
                        g_v[idx] = val;
                    } else {
                        const float ek = __expf(val);
                        g_ek[idx]  = ek;
                        g_ekv[idx] = ek * g_v[idx];
                    }
                }
            }
        }
    }
}

// ---------------------------------------------------------------------------
// AFT core, tf32 tensor cores.
// Per (n,h): num[t,d] = sum_{s<=t} exp(w[h,t,s])*ekv[s,d]; den likewise with ek.
// Block tile: 128 t x 128 d, s-chunks of 16, causal.
// ---------------------------------------------------------------------------
__global__ __launch_bounds__(256)
void aft_tc(const float* __restrict__ w_aft)
{
    __shared__ uint32_t Ws[16][SPAD];   // [s][t]  exp(w), masked, tf32
    __shared__ uint32_t Ek[16][SPAD];   // [s][d]
    __shared__ uint32_t Ev[16][SPAD];   // [s][d]

    const int tid  = threadIdx.x;
    const int lane = tid & 31;
    const int warp = tid >> 5;
    const int wm   = warp >> 2;
    const int wn   = warp & 3;
    const int r    = lane >> 2;
    const int cc   = lane & 3;

    const int bt = gridDim.x - 1 - blockIdx.x;  // heavy tiles first
    const int t0 = bt << 7;
    const int nh = blockIdx.y;
    const int n  = nh >> 3;
    const int h  = nh & 7;

    const float* wbase  = w_aft + ((size_t)h * SEQ + t0) * SEQ;
    const float* ekbase = g_ek  + (size_t)nh * SEQ * HD;
    const float* evbase = g_ekv + (size_t)nh * SEQ * HD;

    float wReg[2][4];
    float4 ekReg[2], evReg[2];

    auto loadChunk = [&](int s0) {
        #pragma unroll
        for (int i = 0; i < 2; i++) {
            int g = tid + (i << 8);
            // w: t = g>>2 (0..127), s4 = (g&3)*4
            int tl = g >> 2, s4 = (g & 3) << 2;
            float4 w4 = *(const float4*)(wbase + (size_t)tl * SEQ + s0 + s4);
            const int tg = t0 + tl;
            wReg[i][0] = (s0 + s4 + 0 <= tg) ? __expf(w4.x) : 0.f;
            wReg[i][1] = (s0 + s4 + 1 <= tg) ? __expf(w4.y) : 0.f;
            wReg[i][2] = (s0 + s4 + 2 <= tg) ? __expf(w4.z) : 0.f;
            wReg[i][3] = (s0 + s4 + 3 <= tg) ? __expf(w4.w) : 0.f;
            // ek/ekv: s = g>>5 (0..15), d4 = (g&31)*4
            int sl = g >> 5, d4 = (g & 31) << 2;
            ekReg[i] = *(const float4*)(ekbase + (size_t)(s0 + sl) * HD + d4);
            evReg[i] = *(const float4*)(evbase + (size_t)(s0 + sl) * HD + d4);
        }
    };
    auto storeChunk = [&]() {
        #pragma unroll
        for (int i = 0; i < 2; i++) {
            int g = tid + (i << 8);
            int tl = g >> 2, s4 = (g & 3) << 2;
            Ws[s4 + 0][tl] = f2tf32(wReg[i][0]);
            Ws[s4 + 1][tl] = f2tf32(wReg[i][1]);
            Ws[s4 + 2][tl] = f2tf32(wReg[i][2]);
            Ws[s4 + 3][tl] = f2tf32(wReg[i][3]);
            int sl = g >> 5, d4 = (g & 31) << 2;
            uint4 k4, v4;
            k4.x = f2tf32(ekReg[i].x); k4.y = f2tf32(ekReg[i].y);
            k4.z = f2tf32(ekReg[i].z); k4.w = f2tf32(ekReg[i].w);
            v4.x = f2tf32(evReg[i].x); v4.y = f2tf32(evReg[i].y);
            v4.z = f2tf32(evReg[i].z); v4.w = f2tf32(evReg[i].w);
            *(uint4*)&Ek[sl][d4] = k4;
            *(uint4*)&Ev[sl][d4] = v4;
        }
    };

    float accN[4][4][4] = {};
    float accD[4][4][4] = {};

    const int nch = (bt + 1) << 3;  // s-chunks of 16 up to diagonal
    loadChunk(0);
    for (int c = 0; c < nch; c++) {
        storeChunk();
        __syncthreads();
        if (c + 1 < nch) loadChunk((c + 1) << 4);

        #pragma unroll
        for (int ks = 0; ks < 2; ks++) {
            const int k8 = ks << 3;
            uint32_t af[4][4], bk[4][2], bv[4][2];
            #pragma unroll
            for (int im = 0; im < 4; im++) {
                const int m0 = (wm << 6) + (im << 4);
                af[im][0] = Ws[k8 + cc    ][m0 + r    ];
                af[im][1] = Ws[k8 + cc    ][m0 + r + 8];
                af[im][2] = Ws[k8 + cc + 4][m0 + r    ];
                af[im][3] = Ws[k8 + cc + 4][m0 + r + 8];
            }
            #pragma unroll
            for (int in = 0; in < 4; in++) {
                const int n0 = (wn << 5) + (in << 3);
                bk[in][0] = Ek[k8 + cc    ][n0 + r];
                bk[in][1] = Ek[k8 + cc + 4][n0 + r];
                bv[in][0] = Ev[k8 + cc    ][n0 + r];
                bv[in][1] = Ev[k8 + cc + 4][n0 + r];
            }
            #pragma unroll
            for (int im = 0; im < 4; im++)
                #pragma unroll
                for (int in = 0; in < 4; in++) {
                    mma_tf32(accN[im][in], af[im][0], af[im][1], af[im][2], af[im][3],
                             bv[in][0], bv[in][1]);
                    mma_tf32(accD[im][in], af[im][0], af[im][1], af[im][2], af[im][3],
                             bk[in][0], bk[in][1]);
                }
        }
        __syncthreads();
    }

    #pragma unroll
    for (int im = 0; im < 4; im++) {
        #pragma unroll
        for (int in = 0; in < 4; in++) {
            #pragma unroll
            for (int e = 0; e < 4; e++) {
                const int t = t0 + (wm << 6) + (im << 4) + r + ((e >> 1) << 3);
                const int d = (wn << 5) + (in << 3) + (cc << 1) + (e & 1);
                g_aft[((size_t)(n * SEQ + t)) * DIM + h * HD + d] =
                    accN[im][in][e] / accD[im][in][e];
            }
        }
    }
}

extern "C" void kernel_launch(void* const* d_in, const int* in_sizes, int n_in,
                              void* d_out, int out_size)
{
    const float* x     = (const float*)d_in[0];
    const float* Wk    = (const float*)d_in[1];
    const float* bk    = (const float*)d_in[2];
    const float* Wv    = (const float*)d_in[3];
    const float* bv    = (const float*)d_in[4];
    const float* w_aft = (const float*)d_in[5];
    const float* Wo    = (const float*)d_in[6];
    const float* bo    = (const float*)d_in[7];
    float* out = (float*)d_out;

    dim3 gg(DIM / 128, MROWS / 128);   // (8, 64)
    gemm_tc<MODE_V><<<gg, 256>>>(x, Wv, bv, nullptr);
    gemm_tc<MODE_K><<<gg, 256>>>(x, Wk, bk, nullptr);
    aft_tc<<<dim3(SEQ / 128, NB * HEADS), 256>>>(w_aft);
    gemm_tc<MODE_OUT><<<gg, 256>>>(nullptr, Wo, bo, out);
}

// round 3
// speedup vs baseline: 2.6435x; 1.2638x over previous
#include <cuda_runtime.h>
#include <cstdint>

#define NB    4
#define SEQ   2048
#define DIM   1024
#define HEADS 8
#define HD    128
#define MROWS (NB*SEQ)

// Scratch (device globals — no allocation allowed)
__device__ float g_v  [(size_t)NB*HEADS*SEQ*HD];
__device__ float g_ek [(size_t)NB*HEADS*SEQ*HD];
__device__ float g_ekv[(size_t)NB*HEADS*SEQ*HD];
__device__ float g_aft[(size_t)MROWS*DIM];

#define MODE_V   0
#define MODE_K   1
#define MODE_OUT 2

__device__ __forceinline__ uint32_t f2tf32(float x) {
    uint32_t r;
    asm("cvt.rna.tf32.f32 %0, %1;" : "=r"(r) : "f"(x));
    return r;
}

__device__ __forceinline__ void mma_tf32(float c[4],
    uint32_t a0, uint32_t a1, uint32_t a2, uint32_t a3,
    uint32_t b0, uint32_t b1)
{
    asm volatile(
        "mma.sync.aligned.m16n8k8.row.col.f32.tf32.tf32.f32 "
        "{%0,%1,%2,%3}, {%4,%5,%6,%7}, {%8,%9}, {%0,%1,%2,%3};\n"
        : "+f"(c[0]), "+f"(c[1]), "+f"(c[2]), "+f"(c[3])
        : "r"(a0), "r"(a1), "r"(a2), "r"(a3), "r"(b0), "r"(b1));
}

__device__ __forceinline__ uint32_t smem_u32(const void* p) {
    return (uint32_t)__cvta_generic_to_shared(p);
}
__device__ __forceinline__ void cp16(uint32_t dst, const void* src) {
    asm volatile("cp.async.ca.shared.global [%0], [%1], 16;\n" :: "r"(dst), "l"(src));
}
__device__ __forceinline__ void cp_commit() {
    asm volatile("cp.async.commit_group;\n");
}
__device__ __forceinline__ void cp_wait0() {
    asm volatile("cp.async.wait_group 0;\n");
}

#define APAD 20    // A row stride (words): [m][k], k-slab 16 + 4 pad
#define BPAD 136   // B row stride (words): [k][n], 128 + 8 pad

// ---------------------------------------------------------------------------
// C[8192,1024] = A[8192,1024] @ B[1024,1024] + bias, tf32 tensor cores.
// Block 128x128, BK=16, 256 threads, warps 2(m) x 4(n), warp tile 64x32.
// cp.async 2-stage pipeline; A stored row-major [m][k] (no transpose needed).
// ---------------------------------------------------------------------------
template<int MODE>
__global__ __launch_bounds__(256)
void gemm_tc(const float* __restrict__ Ain, const float* __restrict__ B,
             const float* __restrict__ bias, float* __restrict__ out)
{
    __shared__ float As[2][128][APAD];
    __shared__ float Bs[2][16][BPAD];

    const float* A = (MODE == MODE_OUT) ? (const float*)g_aft : Ain;

    const int tid  = threadIdx.x;
    const int lane = tid & 31;
    const int warp = tid >> 5;
    const int wm   = warp >> 2;
    const int wn   = warp & 3;
    const int r    = lane >> 2;
    const int cc   = lane & 3;

    const int bm = blockIdx.y << 7;
    const int bn = blockIdx.x << 7;

    // cp.async mapping: thread handles 2 A-float4 + 2 B-float4 per stage
    // A: g = tid + i*256 -> m = g>>2, k4 = (g&3)*4
    // B: g -> k = g>>5, n4 = (g&31)*4
    const int am[2]  = { (tid + 0)   >> 2, (tid + 256) >> 2 };
    const int ak4    = (tid & 3) << 2;
    const int bk_[2] = { (tid + 0)   >> 5, (tid + 256) >> 5 };
    const int bn4    = (tid & 31) << 2;

    const float* Abase = A + (size_t)bm * DIM;
    const float* Bbase = B + bn;

    uint32_t asAddr[2][2], bsAddr[2][2];
    #pragma unroll
    for (int b = 0; b < 2; b++)
        #pragma unroll
        for (int i = 0; i < 2; i++) {
            asAddr[b][i] = smem_u32(&As[b][am[i]][ak4]);
            bsAddr[b][i] = smem_u32(&Bs[b][bk_[i]][bn4]);
        }

    auto issue = [&](int k0, int buf) {
        #pragma unroll
        for (int i = 0; i < 2; i++) {
            cp16(asAddr[buf][i], Abase + (size_t)am[i] * DIM + k0 + ak4);
            cp16(bsAddr[buf][i], Bbase + (size_t)(k0 + bk_[i]) * DIM + bn4);
        }
        cp_commit();
    };

    float acc[4][4][4] = {};

    issue(0, 0);

    const int NT = DIM / 16;   // 64
    const int m0b = wm << 6;
    const int n0b = wn << 5;

    for (int kt = 0; kt < NT; kt++) {
        const int buf = kt & 1;
        cp_wait0();
        __syncthreads();
        if (kt + 1 < NT) issue((kt + 1) << 4, buf ^ 1);

        #pragma unroll
        for (int ks = 0; ks < 2; ks++) {
            const int k8 = ks << 3;
            uint32_t af[4][4], bf[4][2];
            #pragma unroll
            for (int im = 0; im < 4; im++) {
                const int m0 = m0b + (im << 4);
                af[im][0] = f2tf32(As[buf][m0 + r    ][k8 + cc    ]);
                af[im][1] = f2tf32(As[buf][m0 + r + 8][k8 + cc    ]);
                af[im][2] = f2tf32(As[buf][m0 + r    ][k8 + cc + 4]);
                af[im][3] = f2tf32(As[buf][m0 + r + 8][k8 + cc + 4]);
            }
            #pragma unroll
            for (int in = 0; in < 4; in++) {
                const int n0 = n0b + (in << 3);
                bf[in][0] = f2tf32(Bs[buf][k8 + cc    ][n0 + r]);
                bf[in][1] = f2tf32(Bs[buf][k8 + cc + 4][n0 + r]);
            }
            #pragma unroll
            for (int im = 0; im < 4; im++)
                #pragma unroll
                for (int in = 0; in < 4; in++)
                    mma_tf32(acc[im][in], af[im][0], af[im][1], af[im][2], af[im][3],
                             bf[in][0], bf[in][1]);
        }
        __syncthreads();
    }

    // epilogue
    #pragma unroll
    for (int im = 0; im < 4; im++) {
        #pragma unroll
        for (int in = 0; in < 4; in++) {
            #pragma unroll
            for (int e = 0; e < 4; e++) {
                const int row = bm + m0b + (im << 4) + r + ((e >> 1) << 3);
                const int col = bn + n0b + (in << 3) + (cc << 1) + (e & 1);
                const float val = acc[im][in][e] + bias[col];
                if (MODE == MODE_OUT) {
                    out[(size_t)row * DIM + col] = val;
                } else {
                    const int n = row >> 11, s = row & (SEQ - 1);
                    const int h = col >> 7, d = col & 127;
                    const size_t idx = (((size_t)(n * HEADS + h)) * SEQ + s) * HD + d;
                    if (MODE == MODE_V) {
                        g_v[idx] = val;
                    } else {
                        const float ek = __expf(val);
                        g_ek[idx]  = ek;
                        g_ekv[idx] = ek * g_v[idx];
                    }
                }
            }
        }
    }
}

// ---------------------------------------------------------------------------
// AFT core, tf32 tensor cores.
// Per (n,h): num[t,d] = sum_{s<=t} exp(w[h,t,s])*ekv[s,d]; den with ek.
// Block tile: 64 t x 128 d, s-chunks of 16, causal, heavy-first.
// Warps 2(t) x 4(d): warp tile 32x32. Dual accumulators = 64 regs.
// ---------------------------------------------------------------------------
__global__ __launch_bounds__(256)
void aft_tc(const float* __restrict__ w_aft)
{
    __shared__ float Ws[2][64][APAD];    // [t][s] exp(w) masked
    __shared__ float Ek[2][16][BPAD];    // [s][d]
    __shared__ float Ev[2][16][BPAD];

    const int tid  = threadIdx.x;
    const int lane = tid & 31;
    const int warp = tid >> 5;
    const int wm   = warp >> 2;
    const int wn   = warp & 3;
    const int r    = lane >> 2;
    const int cc   = lane & 3;

    const int bt = gridDim.x - 1 - blockIdx.x;   // heavy tiles first
    const int t0 = bt << 6;
    const int nh = blockIdx.y;
    const int n  = nh >> 3;
    const int h  = nh & 7;

    const float* wbase  = w_aft + ((size_t)h * SEQ + t0) * SEQ;
    const float* ekbase = g_ek  + (size_t)nh * SEQ * HD;
    const float* evbase = g_ekv + (size_t)nh * SEQ * HD;

    // w load mapping: 1024 floats/chunk = 256 float4, 1 per thread
    const int w_tl = tid >> 2;          // 0..63
    const int w_s4 = (tid & 3) << 2;
    // ek/ekv cp.async: 512 float4, 2 per thread
    const int e_sl[2] = { (tid + 0) >> 5, (tid + 256) >> 5 };
    const int e_d4    = (tid & 31) << 2;

    uint32_t ekAddr[2][2], evAddr[2][2];
    #pragma unroll
    for (int b = 0; b < 2; b++)
        #pragma unroll
        for (int i = 0; i < 2; i++) {
            ekAddr[b][i] = smem_u32(&Ek[b][e_sl[i]][e_d4]);
            evAddr[b][i] = smem_u32(&Ev[b][e_sl[i]][e_d4]);
        }

    auto issueE = [&](int s0, int buf) {
        #pragma unroll
        for (int i = 0; i < 2; i++) {
            cp16(ekAddr[buf][i], ekbase + (size_t)(s0 + e_sl[i]) * HD + e_d4);
            cp16(evAddr[buf][i], evbase + (size_t)(s0 + e_sl[i]) * HD + e_d4);
        }
        cp_commit();
    };

    float wv[4];
    auto loadW = [&](int s0) {
        float4 w4 = *(const float4*)(wbase + (size_t)w_tl * SEQ + s0 + w_s4);
        const int tg = t0 + w_tl;
        wv[0] = (s0 + w_s4 + 0 <= tg) ? __expf(w4.x) : 0.f;
        wv[1] = (s0 + w_s4 + 1 <= tg) ? __expf(w4.y) : 0.f;
        wv[2] = (s0 + w_s4 + 2 <= tg) ? __expf(w4.z) : 0.f;
        wv[3] = (s0 + w_s4 + 3 <= tg) ? __expf(w4.w) : 0.f;
    };
    auto storeW = [&](int buf) {
        *(float4*)&Ws[buf][w_tl][w_s4] = *(const float4*)wv;
    };

    float accN[2][4][4] = {};
    float accD[2][4][4] = {};

    const int nch = (bt + 1) << 2;   // s-chunks of 16 through the diagonal
    loadW(0);
    issueE(0, 0);

    const int m0b = wm << 5;
    const int n0b = wn << 5;

    for (int c = 0; c < nch; c++) {
        const int buf = c & 1;
        storeW(buf);
        cp_wait0();
        __syncthreads();
        if (c + 1 < nch) {
            loadW((c + 1) << 4);
            issueE((c + 1) << 4, buf ^ 1);
        }

        #pragma unroll
        for (int ks = 0; ks < 2; ks++) {
            const int k8 = ks << 3;
            uint32_t af[2][4], bk[4][2], bv[4][2];
            #pragma unroll
            for (int im = 0; im < 2; im++) {
                const int m0 = m0b + (im << 4);
                af[im][0] = f2tf32(Ws[buf][m0 + r    ][k8 + cc    ]);
                af[im][1] = f2tf32(Ws[buf][m0 + r + 8][k8 + cc    ]);
                af[im][2] = f2tf32(Ws[buf][m0 + r    ][k8 + cc + 4]);
                af[im][3] = f2tf32(Ws[buf][m0 + r + 8][k8 + cc + 4]);
            }
            #pragma unroll
            for (int in = 0; in < 4; in++) {
                const int n0 = n0b + (in << 3);
                bk[in][0] = f2tf32(Ek[buf][k8 + cc    ][n0 + r]);
                bk[in][1] = f2tf32(Ek[buf][k8 + cc + 4][n0 + r]);
                bv[in][0] = f2tf32(Ev[buf][k8 + cc    ][n0 + r]);
                bv[in][1] = f2tf32(Ev[buf][k8 + cc + 4][n0 + r]);
            }
            #pragma unroll
            for (int im = 0; im < 2; im++)
                #pragma unroll
                for (int in = 0; in < 4; in++) {
                    mma_tf32(accN[im][in], af[im][0], af[im][1], af[im][2], af[im][3],
                             bv[in][0], bv[in][1]);
                    mma_tf32(accD[im][in], af[im][0], af[im][1], af[im][2], af[im][3],
                             bk[in][0], bk[in][1]);
                }
        }
        __syncthreads();
    }

    #pragma unroll
    for (int im = 0; im < 2; im++) {
        #pragma unroll
        for (int in = 0; in < 4; in++) {
            #pragma unroll
            for (int e = 0; e < 4; e++) {
                const int t = t0 + m0b + (im << 4) + r + ((e >> 1) << 3);
                const int d = n0b + (in << 3) + (cc << 1) + (e & 1);
                g_aft[((size_t)(n * SEQ + t)) * DIM + h * HD + d] =
                    accN[im][in][e] / accD[im][in][e];
            }
        }
    }
}

extern "C" void kernel_launch(void* const* d_in, const int* in_sizes, int n_in,
                              void* d_out, int out_size)
{
    const float* x     = (const float*)d_in[0];
    const float* Wk    = (const float*)d_in[1];
    const float* bk    = (const float*)d_in[2];
    const float* Wv    = (const float*)d_in[3];
    const float* bv    = (const float*)d_in[4];
    const float* w_aft = (const float*)d_in[5];
    const float* Wo    = (const float*)d_in[6];
    const float* bo    = (const float*)d_in[7];
    float* out = (float*)d_out;

    dim3 gg(DIM / 128, MROWS / 128);   // (8, 64)
    gemm_tc<MODE_V><<<gg, 256>>>(x, Wv, bv, nullptr);
    gemm_tc<MODE_K><<<gg, 256>>>(x, Wk, bk, nullptr);
    aft_tc<<<dim3(SEQ / 64, NB * HEADS), 256>>>(w_aft);
    gemm_tc<MODE_OUT><<<gg, 256>>>(nullptr, Wo, bo, out);
}

// round 4
// speedup vs baseline: 2.6606x; 1.0065x over previous
#include <cuda_runtime.h>
#include <cstdint>

#define NB    4
#define SEQ   2048
#define DIM   1024
#define HEADS 8
#define HD    128
#define MROWS (NB*SEQ)

// Scratch (device globals — no allocation allowed)
__device__ float g_v  [(size_t)NB*HEADS*SEQ*HD];
__device__ float g_ek [(size_t)NB*HEADS*SEQ*HD];
__device__ float g_ekv[(size_t)NB*HEADS*SEQ*HD];
__device__ float g_aft[(size_t)MROWS*DIM];

#define MODE_V   0
#define MODE_K   1
#define MODE_OUT 2

__device__ __forceinline__ uint32_t f2tf32(float x) {
    uint32_t r;
    asm("cvt.rna.tf32.f32 %0, %1;" : "=r"(r) : "f"(x));
    return r;
}

__device__ __forceinline__ void mma_tf32(float c[4],
    uint32_t a0, uint32_t a1, uint32_t a2, uint32_t a3,
    uint32_t b0, uint32_t b1)
{
    asm volatile(
        "mma.sync.aligned.m16n8k8.row.col.f32.tf32.tf32.f32 "
        "{%0,%1,%2,%3}, {%4,%5,%6,%7}, {%8,%9}, {%0,%1,%2,%3};\n"
        : "+f"(c[0]), "+f"(c[1]), "+f"(c[2]), "+f"(c[3])
        : "r"(a0), "r"(a1), "r"(a2), "r"(a3), "r"(b0), "r"(b1));
}

__device__ __forceinline__ uint32_t smem_u32(const void* p) {
    return (uint32_t)__cvta_generic_to_shared(p);
}
__device__ __forceinline__ void cp16(uint32_t dst, const void* src) {
    asm volatile("cp.async.ca.shared.global [%0], [%1], 16;\n" :: "r"(dst), "l"(src));
}
__device__ __forceinline__ void cp_commit() {
    asm volatile("cp.async.commit_group;\n");
}
__device__ __forceinline__ void cp_wait0() {
    asm volatile("cp.async.wait_group 0;\n");
}

#define APAD 20    // A row stride (words): [m][k], k-slab 16 + 4 pad
#define BPAD 136   // B row stride (words): [k][n], 128 + 8 pad

// ---------------------------------------------------------------------------
// C[8192,1024] = A[8192,1024] @ B[1024,1024] + bias, tf32 tensor cores.
// Block 128x128, BK=16, 256 threads, warps 2(m) x 4(n), warp tile 64x32.
// cp.async 2-stage pipeline; A stored row-major [m][k] (no transpose needed).
// ---------------------------------------------------------------------------
template<int MODE>
__global__ __launch_bounds__(256)
void gemm_tc(const float* __restrict__ Ain, const float* __restrict__ B,
             const float* __restrict__ bias, float* __restrict__ out)
{
    __shared__ float As[2][128][APAD];
    __shared__ float Bs[2][16][BPAD];

    const float* A = (MODE == MODE_OUT) ? (const float*)g_aft : Ain;

    const int tid  = threadIdx.x;
    const int lane = tid & 31;
    const int warp = tid >> 5;
    const int wm   = warp >> 2;
    const int wn   = warp & 3;
    const int r    = lane >> 2;
    const int cc   = lane & 3;

    const int bm = blockIdx.y << 7;
    const int bn = blockIdx.x << 7;

    // cp.async mapping: thread handles 2 A-float4 + 2 B-float4 per stage
    // A: g = tid + i*256 -> m = g>>2, k4 = (g&3)*4
    // B: g -> k = g>>5, n4 = (g&31)*4
    const int am[2]  = { (tid + 0)   >> 2, (tid + 256) >> 2 };
    const int ak4    = (tid & 3) << 2;
    const int bk_[2] = { (tid + 0)   >> 5, (tid + 256) >> 5 };
    const int bn4    = (tid & 31) << 2;

    const float* Abase = A + (size_t)bm * DIM;
    const float* Bbase = B + bn;

    uint32_t asAddr[2][2], bsAddr[2][2];
    #pragma unroll
    for (int b = 0; b < 2; b++)
        #pragma unroll
        for (int i = 0; i < 2; i++) {
            asAddr[b][i] = smem_u32(&As[b][am[i]][ak4]);
            bsAddr[b][i] = smem_u32(&Bs[b][bk_[i]][bn4]);
        }

    auto issue = [&](int k0, int buf) {
        #pragma unroll
        for (int i = 0; i < 2; i++) {
            cp16(asAddr[buf][i], Abase + (size_t)am[i] * DIM + k0 + ak4);
            cp16(bsAddr[buf][i], Bbase + (size_t)(k0 + bk_[i]) * DIM + bn4);
        }
        cp_commit();
    };

    float acc[4][4][4] = {};

    issue(0, 0);

    const int NT = DIM / 16;   // 64
    const int m0b = wm << 6;
    const int n0b = wn << 5;

    for (int kt = 0; kt < NT; kt++) {
        const int buf = kt & 1;
        cp_wait0();
        __syncthreads();
        if (kt + 1 < NT) issue((kt + 1) << 4, buf ^ 1);

        #pragma unroll
        for (int ks = 0; ks < 2; ks++) {
            const int k8 = ks << 3;
            uint32_t af[4][4], bf[4][2];
            #pragma unroll
            for (int im = 0; im < 4; im++) {
                const int m0 = m0b + (im << 4);
                af[im][0] = f2tf32(As[buf][m0 + r    ][k8 + cc    ]);
                af[im][1] = f2tf32(As[buf][m0 + r + 8][k8 + cc    ]);
                af[im][2] = f2tf32(As[buf][m0 + r    ][k8 + cc + 4]);
                af[im][3] = f2tf32(As[buf][m0 + r + 8][k8 + cc + 4]);
            }
            #pragma unroll
            for (int in = 0; in < 4; in++) {
                const int n0 = n0b + (in << 3);
                bf[in][0] = f2tf32(Bs[buf][k8 + cc    ][n0 + r]);
                bf[in][1] = f2tf32(Bs[buf][k8 + cc + 4][n0 + r]);
            }
            #pragma unroll
            for (int im = 0; im < 4; im++)
                #pragma unroll
                for (int in = 0; in < 4; in++)
                    mma_tf32(acc[im][in], af[im][0], af[im][1], af[im][2], af[im][3],
                             bf[in][0], bf[in][1]);
        }
        __syncthreads();
    }

    // epilogue
    #pragma unroll
    for (int im = 0; im < 4; im++) {
        #pragma unroll
        for (int in = 0; in < 4; in++) {
            #pragma unroll
            for (int e = 0; e < 4; e++) {
                const int row = bm + m0b + (im << 4) + r + ((e >> 1) << 3);
                const int col = bn + n0b + (in << 3) + (cc << 1) + (e & 1);
                const float val = acc[im][in][e] + bias[col];
                if (MODE == MODE_OUT) {
                    out[(size_t)row * DIM + col] = val;
                } else {
                    const int n = row >> 11, s = row & (SEQ - 1);
                    const int h = col >> 7, d = col & 127;
                    const size_t idx = (((size_t)(n * HEADS + h)) * SEQ + s) * HD + d;
                    if (MODE == MODE_V) {
                        g_v[idx] = val;
                    } else {
                        const float ek = __expf(val);
                        g_ek[idx]  = ek;
                        g_ekv[idx] = ek * g_v[idx];
                    }
                }
            }
        }
    }
}

// ---------------------------------------------------------------------------
// AFT core, tf32 tensor cores.
// Per (n,h): num[t,d] = sum_{s<=t} exp(w[h,t,s])*ekv[s,d]; den with ek.
// Block tile: 64 t x 128 d, s-chunks of 16, causal, heavy-first.
// Warps 2(t) x 4(d): warp tile 32x32. Dual accumulators = 64 regs.
// ---------------------------------------------------------------------------
__global__ __launch_bounds__(256)
void aft_tc(const float* __restrict__ w_aft)
{
    __shared__ float Ws[2][64][APAD];    // [t][s] exp(w) masked
    __shared__ float Ek[2][16][BPAD];    // [s][d]
    __shared__ float Ev[2][16][BPAD];

    const int tid  = threadIdx.x;
    const int lane = tid & 31;
    const int warp = tid >> 5;
    const int wm   = warp >> 2;
    const int wn   = warp & 3;
    const int r    = lane >> 2;
    const int cc   = lane & 3;

    const int bt = gridDim.x - 1 - blockIdx.x;   // heavy tiles first
    const int t0 = bt << 6;
    const int nh = blockIdx.y;
    const int n  = nh >> 3;
    const int h  = nh & 7;

    const float* wbase  = w_aft + ((size_t)h * SEQ + t0) * SEQ;
    const float* ekbase = g_ek  + (size_t)nh * SEQ * HD;
    const float* evbase = g_ekv + (size_t)nh * SEQ * HD;

    // w load mapping: 1024 floats/chunk = 256 float4, 1 per thread
    const int w_tl = tid >> 2;          // 0..63
    const int w_s4 = (tid & 3) << 2;
    // ek/ekv cp.async: 512 float4, 2 per thread
    const int e_sl[2] = { (tid + 0) >> 5, (tid + 256) >> 5 };
    const int e_d4    = (tid & 31) << 2;

    uint32_t ekAddr[2][2], evAddr[2][2];
    #pragma unroll
    for (int b = 0; b < 2; b++)
        #pragma unroll
        for (int i = 0; i < 2; i++) {
            ekAddr[b][i] = smem_u32(&Ek[b][e_sl[i]][e_d4]);
            evAddr[b][i] = smem_u32(&Ev[b][e_sl[i]][e_d4]);
        }

    auto issueE = [&](int s0, int buf) {
        #pragma unroll
        for (int i = 0; i < 2; i++) {
            cp16(ekAddr[buf][i], ekbase + (size_t)(s0 + e_sl[i]) * HD + e_d4);
            cp16(evAddr[buf][i], evbase + (size_t)(s0 + e_sl[i]) * HD + e_d4);
        }
        cp_commit();
    };

    float wv[4];
    auto loadW = [&](int s0) {
        float4 w4 = *(const float4*)(wbase + (size_t)w_tl * SEQ + s0 + w_s4);
        const int tg = t0 + w_tl;
        wv[0] = (s0 + w_s4 + 0 <= tg) ? __expf(w4.x) : 0.f;
        wv[1] = (s0 + w_s4 + 1 <= tg) ? __expf(w4.y) : 0.f;
        wv[2] = (s0 + w_s4 + 2 <= tg) ? __expf(w4.z) : 0.f;
        wv[3] = (s0 + w_s4 + 3 <= tg) ? __expf(w4.w) : 0.f;
    };
    auto storeW = [&](int buf) {
        *(float4*)&Ws[buf][w_tl][w_s4] = *(const float4*)wv;
    };

    float accN[2][4][4] = {};
    float accD[2][4][4] = {};

    const int nch = (bt + 1) << 2;   // s-chunks of 16 through the diagonal
    loadW(0);
    issueE(0, 0);

    const int m0b = wm << 5;
    const int n0b = wn << 5;

    for (int c = 0; c < nch; c++) {
        const int buf = c & 1;
        storeW(buf);
        cp_wait0();
        __syncthreads();
        if (c + 1 < nch) {
            loadW((c + 1) << 4);
            issueE((c + 1) << 4, buf ^ 1);
        }

        #pragma unroll
        for (int ks = 0; ks < 2; ks++) {
            const int k8 = ks << 3;
            uint32_t af[2][4], bk[4][2], bv[4][2];
            #pragma unroll
            for (int im = 0; im < 2; im++) {
                const int m0 = m0b + (im << 4);
                af[im][0] = f2tf32(Ws[buf][m0 + r    ][k8 + cc    ]);
                af[im][1] = f2tf32(Ws[buf][m0 + r + 8][k8 + cc    ]);
                af[im][2] = f2tf32(Ws[buf][m0 + r    ][k8 + cc + 4]);
                af[im][3] = f2tf32(Ws[buf][m0 + r + 8][k8 + cc + 4]);
            }
            #pragma unroll
            for (int in = 0; in < 4; in++) {
                const int n0 = n0b + (in << 3);
                bk[in][0] = f2tf32(Ek[buf][k8 + cc    ][n0 + r]);
                bk[in][1] = f2tf32(Ek[buf][k8 + cc + 4][n0 + r]);
                bv[in][0] = f2tf32(Ev[buf][k8 + cc    ][n0 + r]);
                bv[in][1] = f2tf32(Ev[buf][k8 + cc + 4][n0 + r]);
            }
            #pragma unroll
            for (int im = 0; im < 2; im++)
                #pragma unroll
                for (int in = 0; in < 4; in++) {
                    mma_tf32(accN[im][in], af[im][0], af[im][1], af[im][2], af[im][3],
                             bv[in][0], bv[in][1]);
                    mma_tf32(accD[im][in], af[im][0], af[im][1], af[im][2], af[im][3],
                             bk[in][0], bk[in][1]);
                }
        }
        __syncthreads();
    }

    #pragma unroll
    for (int im = 0; im < 2; im++) {
        #pragma unroll
        for (int in = 0; in < 4; in++) {
            #pragma unroll
            for (int e = 0; e < 4; e++) {
                const int t = t0 + m0b + (im << 4) + r + ((e >> 1) << 3);
                const int d = n0b + (in << 3) + (cc << 1) + (e & 1);
                g_aft[((size_t)(n * SEQ + t)) * DIM + h * HD + d] =
                    accN[im][in][e] / accD[im][in][e];
            }
        }
    }
}

extern "C" void kernel_launch(void* const* d_in, const int* in_sizes, int n_in,
                              void* d_out, int out_size)
{
    const float* x     = (const float*)d_in[0];
    const float* Wk    = (const float*)d_in[1];
    const float* bk    = (const float*)d_in[2];
    const float* Wv    = (const float*)d_in[3];
    const float* bv    = (const float*)d_in[4];
    const float* w_aft = (const float*)d_in[5];
    const float* Wo    = (const float*)d_in[6];
    const float* bo    = (const float*)d_in[7];
    float* out = (float*)d_out;

    dim3 gg(DIM / 128, MROWS / 128);   // (8, 64)
    gemm_tc<MODE_V><<<gg, 256>>>(x, Wv, bv, nullptr);
    gemm_tc<MODE_K><<<gg, 256>>>(x, Wk, bk, nullptr);
    aft_tc<<<dim3(SEQ / 64, NB * HEADS), 256>>>(w_aft);
    gemm_tc<MODE_OUT><<<gg, 256>>>(nullptr, Wo, bo, out);
}

// round 5
// speedup vs baseline: 2.6680x; 1.0028x over previous
#include <cuda_runtime.h>
#include <cstdint>

#define NB    4
#define SEQ   2048
#define DIM   1024
#define HEADS 8
#define HD    128
#define MROWS (NB*SEQ)

// Scratch (device globals — no allocation allowed)
__device__ float g_v  [(size_t)NB*HEADS*SEQ*HD];
__device__ float g_ek [(size_t)NB*HEADS*SEQ*HD];
__device__ float g_ekv[(size_t)NB*HEADS*SEQ*HD];
__device__ float g_aft[(size_t)MROWS*DIM];
__device__ float g_xr [(size_t)MROWS*DIM];     // tf32-rounded x
__device__ float g_wkr[(size_t)DIM*DIM];       // tf32-rounded weights
__device__ float g_wvr[(size_t)DIM*DIM];
__device__ float g_wor[(size_t)DIM*DIM];

#define MODE_V   0
#define MODE_K   1
#define MODE_OUT 2

__device__ __forceinline__ uint32_t f2tf32(float x) {
    uint32_t r;
    asm("cvt.rna.tf32.f32 %0, %1;" : "=r"(r) : "f"(x));
    return r;
}
__device__ __forceinline__ float f2tf32f(float x) {
    return __uint_as_float(f2tf32(x));
}

__device__ __forceinline__ void mma_tf32(float c[4],
    uint32_t a0, uint32_t a1, uint32_t a2, uint32_t a3,
    uint32_t b0, uint32_t b1)
{
    asm volatile(
        "mma.sync.aligned.m16n8k8.row.col.f32.tf32.tf32.f32 "
        "{%0,%1,%2,%3}, {%4,%5,%6,%7}, {%8,%9}, {%0,%1,%2,%3};\n"
        : "+f"(c[0]), "+f"(c[1]), "+f"(c[2]), "+f"(c[3])
        : "r"(a0), "r"(a1), "r"(a2), "r"(a3), "r"(b0), "r"(b1));
}

__device__ __forceinline__ uint32_t smem_u32(const void* p) {
    return (uint32_t)__cvta_generic_to_shared(p);
}
__device__ __forceinline__ void cp16(uint32_t dst, const void* src) {
    asm volatile("cp.async.ca.shared.global [%0], [%1], 16;\n" :: "r"(dst), "l"(src));
}
__device__ __forceinline__ void cp_commit() {
    asm volatile("cp.async.commit_group;\n");
}
__device__ __forceinline__ void cp_wait2() {
    asm volatile("cp.async.wait_group 2;\n");
}

// ---------------------------------------------------------------------------
// prep: tf32-round x and the three weight matrices into scratch.
// ---------------------------------------------------------------------------
__global__ __launch_bounds__(256)
void prep_round(const float4* __restrict__ x, const float4* __restrict__ wk,
                const float4* __restrict__ wv, const float4* __restrict__ wo)
{
    const size_t X4 = (size_t)MROWS * DIM / 4;   // 2,097,152
    size_t i = (size_t)blockIdx.x * blockDim.x + threadIdx.x;
    const float4* src;
    float4* dst;
    if (i < X4) {
        src = x + i;
        dst = (float4*)g_xr + i;
    } else {
        size_t j = i - X4;
        int seg = (int)(j >> 18);                 // W4 = 2^18 float4 per weight
        size_t o = j & ((1u << 18) - 1);
        src = (seg == 0 ? wk : (seg == 1 ? wv : wo)) + o;
        dst = (float4*)(seg == 0 ? g_wkr : (seg == 1 ? g_wvr : g_wor)) + o;
    }
    float4 v = *src;
    float4 r;
    r.x = f2tf32f(v.x); r.y = f2tf32f(v.y);
    r.z = f2tf32f(v.z); r.w = f2tf32f(v.w);
    *dst = r;
}

// ---------------------------------------------------------------------------
// GEMM: C[8192,1024] = A @ B + bias, tf32 tensor cores, pre-rounded inputs.
// Block 128x128, BK=16, 256 threads, warps 2(m) x 4(n), warp tile 64x32.
// 4-stage cp.async pipeline, dynamic smem. A stored [m][k] pad 20,
// B stored [k][n] pad 136 (both provably bank-conflict-free for fragments).
// ---------------------------------------------------------------------------
#define A_STRIDE 20
#define B_STRIDE 136
#define A_STG (128*A_STRIDE)          // 2560 words/stage
#define B_STG (16*B_STRIDE)           // 2176 words/stage
#define B_OFF (4*A_STG)               // 10240
#define GEMM_SMEM_W (4*A_STG + 4*B_STG)
#define GEMM_SMEM_B (GEMM_SMEM_W*4)   // 75776 bytes

template<int MODE>
__global__ __launch_bounds__(256)
void gemm_tc(const float* __restrict__ bias, float* __restrict__ out)
{
    extern __shared__ uint32_t sm[];

    const float* A = (MODE == MODE_OUT) ? g_aft : g_xr;
    const float* B = (MODE == MODE_V) ? g_wvr : (MODE == MODE_K ? g_wkr : g_wor);

    const int tid  = threadIdx.x;
    const int lane = tid & 31;
    const int warp = tid >> 5;
    const int wm   = warp >> 2;
    const int wn   = warp & 3;
    const int r    = lane >> 2;
    const int cc   = lane & 3;

    const int bm = blockIdx.y << 7;
    const int bn = blockIdx.x << 7;

    // cp.async mapping: 2 A-float4 + 2 B-float4 per thread per stage
    const int am[2]  = { tid >> 2, 64 + (tid >> 2) };
    const int ak4    = (tid & 3) << 2;
    const int bk_[2] = { tid >> 5, 8 + (tid >> 5) };
    const int bn4    = (tid & 31) << 2;

    const float* Abase = A + (size_t)bm * DIM;
    const float* Bbase = B + bn;

    uint32_t aAddr[2], bAddr[2];
    #pragma unroll
    for (int i = 0; i < 2; i++) {
        aAddr[i] = smem_u32(&sm[am[i]*A_STRIDE + ak4]);
        bAddr[i] = smem_u32(&sm[B_OFF + bk_[i]*B_STRIDE + bn4]);
    }

    auto issue = [&](int k0, int st) {
        const uint32_t ao = st * (A_STG*4);
        const uint32_t bo = st * (B_STG*4);
        #pragma unroll
        for (int i = 0; i < 2; i++) {
            cp16(aAddr[i] + ao, Abase + (size_t)am[i]*DIM + k0 + ak4);
            cp16(bAddr[i] + bo, Bbase + (size_t)(k0 + bk_[i])*DIM + bn4);
        }
        cp_commit();
    };

    float acc[4][4][4] = {};

    issue(0, 0); issue(16, 1); issue(32, 2);

    const int NT = DIM / 16;   // 64
    const int m0b = wm << 6;
    const int n0b = wn << 5;

    for (int kt = 0; kt < NT; kt++) {
        const int buf = kt & 3;
        cp_wait2();
        __syncthreads();
        if (kt + 3 < NT) issue((kt + 3) << 4, (kt + 3) & 3);
        else cp_commit();   // empty group keeps wait arithmetic exact

        const uint32_t* Ab = sm + buf*A_STG;
        const uint32_t* Bb = sm + B_OFF + buf*B_STG;

        #pragma unroll
        for (int ks = 0; ks < 2; ks++) {
            const int k8 = ks << 3;
            uint32_t af[4][4], bf[4][2];
            #pragma unroll
            for (int im = 0; im < 4; im++) {
                const int m0 = m0b + (im << 4);
                af[im][0] = Ab[(m0 + r    )*A_STRIDE + k8 + cc    ];
                af[im][1] = Ab[(m0 + r + 8)*A_STRIDE + k8 + cc    ];
                af[im][2] = Ab[(m0 + r    )*A_STRIDE + k8 + cc + 4];
                af[im][3] = Ab[(m0 + r + 8)*A_STRIDE + k8 + cc + 4];
            }
            #pragma unroll
            for (int in = 0; in < 4; in++) {
                const int n0 = n0b + (in << 3);
                bf[in][0] = Bb[(k8 + cc    )*B_STRIDE + n0 + r];
                bf[in][1] = Bb[(k8 + cc + 4)*B_STRIDE + n0 + r];
            }
            #pragma unroll
            for (int im = 0; im < 4; im++)
                #pragma unroll
                for (int in = 0; in < 4; in++)
                    mma_tf32(acc[im][in], af[im][0], af[im][1], af[im][2], af[im][3],
                             bf[in][0], bf[in][1]);
        }
    }

    // epilogue
    #pragma unroll
    for (int im = 0; im < 4; im++) {
        #pragma unroll
        for (int in = 0; in < 4; in++) {
            #pragma unroll
            for (int e = 0; e < 4; e++) {
                const int row = bm + m0b + (im << 4) + r + ((e >> 1) << 3);
                const int col = bn + n0b + (in << 3) + (cc << 1) + (e & 1);
                const float val = acc[im][in][e] + bias[col];
                if (MODE == MODE_OUT) {
                    out[(size_t)row * DIM + col] = val;
                } else {
                    const int n = row >> 11, s = row & (SEQ - 1);
                    const int h = col >> 7, d = col & 127;
                    const size_t idx = (((size_t)(n * HEADS + h)) * SEQ + s) * HD + d;
                    if (MODE == MODE_V) {
                        g_v[idx] = val;
                    } else {
                        const float ek = __expf(val);
                        g_ek[idx]  = f2tf32f(ek);              // pre-rounded
                        g_ekv[idx] = f2tf32f(ek * g_v[idx]);   // pre-rounded
                    }
                }
            }
        }
    }
}

// ---------------------------------------------------------------------------
// AFT core: per (n,h), num/den causal weighted sums, tf32 tensor cores.
// Block 64t x 128d, warps 2(t) x 4(d), s-chunks of 16, heavy-first.
// 4-stage cp.async for ek/ekv, 2-slot smem + reg pipeline for exp(w).
// ---------------------------------------------------------------------------
#define W_STRIDE 20
#define W_STG (64*W_STRIDE)            // 1280 words/slot (2 slots)
#define E_OFF (2*W_STG)                // 2560
#define E_STG (16*B_STRIDE)            // 2176 words/stage
#define EV_OFF (E_OFF + 4*E_STG)       // 11264
#define AFT_SMEM_W (EV_OFF + 4*E_STG)  // 19968
#define AFT_SMEM_B (AFT_SMEM_W*4)      // 79872 bytes

__global__ __launch_bounds__(256)
void aft_tc(const float* __restrict__ w_aft)
{
    extern __shared__ uint32_t sm[];

    const int tid  = threadIdx.x;
    const int lane = tid & 31;
    const int warp = tid >> 5;
    const int wm   = warp >> 2;
    const int wn   = warp & 3;
    const int r    = lane >> 2;
    const int cc   = lane & 3;

    const int bt = gridDim.x - 1 - blockIdx.x;   // heavy tiles first
    const int t0 = bt << 6;
    const int nh = blockIdx.y;
    const int n  = nh >> 3;
    const int h  = nh & 7;

    const float* wbase  = w_aft + ((size_t)h * SEQ + t0) * SEQ;
    const float* ekbase = g_ek  + (size_t)nh * SEQ * HD;
    const float* evbase = g_ekv + (size_t)nh * SEQ * HD;

    const int w_tl = tid >> 2;           // 0..63
    const int w_s4 = (tid & 3) << 2;
    const int e_sl[2] = { tid >> 5, 8 + (tid >> 5) };
    const int e_d4    = (tid & 31) << 2;

    uint32_t ekAddr[2], evAddr[2], wAddr;
    #pragma unroll
    for (int i = 0; i < 2; i++) {
        ekAddr[i] = smem_u32(&sm[E_OFF  + e_sl[i]*B_STRIDE + e_d4]);
        evAddr[i] = smem_u32(&sm[EV_OFF + e_sl[i]*B_STRIDE + e_d4]);
    }
    wAddr = smem_u32(&sm[w_tl*W_STRIDE + w_s4]);

    auto issueE = [&](int s0, int st) {
        const uint32_t eo = st * (E_STG*4);
        #pragma unroll
        for (int i = 0; i < 2; i++) {
            cp16(ekAddr[i] + eo, ekbase + (size_t)(s0 + e_sl[i]) * HD + e_d4);
            cp16(evAddr[i] + eo, evbase + (size_t)(s0 + e_sl[i]) * HD + e_d4);
        }
        cp_commit();
    };

    uint32_t wv[4];
    auto loadW = [&](int s0) {
        float4 w4 = *(const float4*)(wbase + (size_t)w_tl * SEQ + s0 + w_s4);
        const int tg = t0 + w_tl;
        wv[0] = (s0 + w_s4 + 0 <= tg) ? f2tf32(__expf(w4.x)) : 0u;
        wv[1] = (s0 + w_s4 + 1 <= tg) ? f2tf32(__expf(w4.y)) : 0u;
        wv[2] = (s0 + w_s4 + 2 <= tg) ? f2tf32(__expf(w4.z)) : 0u;
        wv[3] = (s0 + w_s4 + 3 <= tg) ? f2tf32(__expf(w4.w)) : 0u;
    };
    auto storeW = [&](int slot) {
        uint4 u = { wv[0], wv[1], wv[2], wv[3] };
        *(uint4*)(sm + slot*W_STG + w_tl*W_STRIDE + w_s4) = u;
        (void)wAddr;
    };

    float accN[2][4][4] = {};
    float accD[2][4][4] = {};

    const int nch = (bt + 1) << 2;   // s-chunks of 16 through the diagonal (>=4)
    loadW(0);
    issueE(0, 0); issueE(16, 1); issueE(32, 2);

    const int m0b = wm << 5;
    const int n0b = wn << 5;

    for (int c = 0; c < nch; c++) {
        const int wslot = c & 1;
        const int ebuf  = c & 3;
        storeW(wslot);
        cp_wait2();
        __syncthreads();
        if (c + 3 < nch) issueE((c + 3) << 4, (c + 3) & 3);
        else cp_commit();
        if (c + 1 < nch) loadW((c + 1) << 4);

        const uint32_t* Wb = sm + wslot*W_STG;
        const uint32_t* Kb = sm + E_OFF  + ebuf*E_STG;
        const uint32_t* Vb = sm + EV_OFF + ebuf*E_STG;

        #pragma unroll
        for (int ks = 0; ks < 2; ks++) {
            const int k8 = ks << 3;
            uint32_t af[2][4], bk[4][2], bv[4][2];
            #pragma unroll
            for (int im = 0; im < 2; im++) {
                const int m0 = m0b + (im << 4);
                af[im][0] = Wb[(m0 + r    )*W_STRIDE + k8 + cc    ];
                af[im][1] = Wb[(m0 + r + 8)*W_STRIDE + k8 + cc    ];
                af[im][2] = Wb[(m0 + r    )*W_STRIDE + k8 + cc + 4];
                af[im][3] = Wb[(m0 + r + 8)*W_STRIDE + k8 + cc + 4];
            }
            #pragma unroll
            for (int in = 0; in < 4; in++) {
                const int n0 = n0b + (in << 3);
                bk[in][0] = Kb[(k8 + cc    )*B_STRIDE + n0 + r];
                bk[in][1] = Kb[(k8 + cc + 4)*B_STRIDE + n0 + r];
                bv[in][0] = Vb[(k8 + cc    )*B_STRIDE + n0 + r];
                bv[in][1] = Vb[(k8 + cc + 4)*B_STRIDE + n0 + r];
            }
            #pragma unroll
            for (int im = 0; im < 2; im++)
                #pragma unroll
                for (int in = 0; in < 4; in++) {
                    mma_tf32(accN[im][in], af[im][0], af[im][1], af[im][2], af[im][3],
                             bv[in][0], bv[in][1]);
                    mma_tf32(accD[im][in], af[im][0], af[im][1], af[im][2], af[im][3],
                             bk[in][0], bk[in][1]);
                }
        }
        __syncthreads();
    }

    #pragma unroll
    for (int im = 0; im < 2; im++) {
        #pragma unroll
        for (int in = 0; in < 4; in++) {
            #pragma unroll
            for (int e = 0; e < 4; e++) {
                const int t = t0 + m0b + (im << 4) + r + ((e >> 1) << 3);
                const int d = n0b + (in << 3) + (cc << 1) + (e & 1);
                g_aft[((size_t)(n * SEQ + t)) * DIM + h * HD + d] =
                    f2tf32f(accN[im][in][e] / accD[im][in][e]);   // pre-rounded for OUT gemm
            }
        }
    }
}

extern "C" void kernel_launch(void* const* d_in, const int* in_sizes, int n_in,
                              void* d_out, int out_size)
{
    const float* x     = (const float*)d_in[0];
    const float* Wk    = (const float*)d_in[1];
    const float* bk    = (const float*)d_in[2];
    const float* Wv    = (const float*)d_in[3];
    const float* bv    = (const float*)d_in[4];
    const float* w_aft = (const float*)d_in[5];
    const float* Wo    = (const float*)d_in[6];
    const float* bo    = (const float*)d_in[7];
    float* out = (float*)d_out;

    cudaFuncSetAttribute(gemm_tc<MODE_V>,   cudaFuncAttributeMaxDynamicSharedMemorySize, GEMM_SMEM_B);
    cudaFuncSetAttribute(gemm_tc<MODE_K>,   cudaFuncAttributeMaxDynamicSharedMemorySize, GEMM_SMEM_B);
    cudaFuncSetAttribute(gemm_tc<MODE_OUT>, cudaFuncAttributeMaxDynamicSharedMemorySize, GEMM_SMEM_B);
    cudaFuncSetAttribute(aft_tc,            cudaFuncAttributeMaxDynamicSharedMemorySize, AFT_SMEM_B);

    prep_round<<<11264, 256>>>((const float4*)x, (const float4*)Wk,
                               (const float4*)Wv, (const float4*)Wo);

    dim3 gg(DIM / 128, MROWS / 128);   // (8, 64)
    gemm_tc<MODE_V><<<gg, 256, GEMM_SMEM_B>>>(bv, nullptr);
    gemm_tc<MODE_K><<<gg, 256, GEMM_SMEM_B>>>(bk, nullptr);
    aft_tc<<<dim3(SEQ / 64, NB * HEADS), 256, AFT_SMEM_B>>>(w_aft);
    gemm_tc<MODE_OUT><<<gg, 256, GEMM_SMEM_B>>>(bo, out);
}